// round 2
// baseline (speedup 1.0000x reference)
#include <cuda_runtime.h>
#include <cuda_bf16.h>
#include <cstdint>
#include <cstddef>

// Problem constants
// X:(2,2048,16,64) A:(2,2048,16) B,C:(2,2048,16,64)
// r,k,v,w,bonus:(32,2048,64)  out:(2,2048,1024) f32

// ---------------- device scratch (static globals; no allocation) ------------
__device__ float g_states[2*32*16*64*64];   // per-chunk states (b,c,h,p,n)
__device__ float g_R[2*32*16*64*64];        // prefix state entering chunk c
__device__ float g_eA[1024*64];             // exp(cumA[l]) per (b,c,h)
__device__ float g_expsA[32*32];            // exp(chunk-sum A) per (b,h,c)

// ---------------- cp.async helpers ------------------------------------------
__device__ __forceinline__ void cp_async16(float* dst, const float* src) {
    unsigned s = (unsigned)__cvta_generic_to_shared(dst);
    asm volatile("cp.async.cg.shared.global [%0], [%1], 16;\n" :: "r"(s), "l"(src));
}
__device__ __forceinline__ void cp_commit() { asm volatile("cp.async.commit_group;\n"); }
__device__ __forceinline__ void cp_wait1()  { asm volatile("cp.async.wait_group 1;\n" ::: "memory"); }
__device__ __forceinline__ void cp_wait0()  { asm volatile("cp.async.wait_group 0;\n" ::: "memory"); }

// ============================================================================
// WKV kernel: 32 blocks (one per batch-head), 256 threads.
// thread t = (i = t>>2, jq = t&3): row i, columns [jq*16, jq*16+16)
// state S[i][j] in registers.
// Recurrence per step l:
//   Sk_i = sum_j S[i,j] k_j
//   delta_j = v_j - Sk_j
//   S[i,j] = S[i,j]*w_i + (bonus_i*k_i)*delta_j
//   y_i = r_i*(w_i*Sk_i + bonus_i*k_i*sum_j delta_j k_j)
// Writes out (pure store) -> must run BEFORE SSD kernels that RMW out.
// ============================================================================
__global__ void __launch_bounds__(256, 1) wkv_kernel(
    const float* __restrict__ rr, const float* __restrict__ kk_g,
    const float* __restrict__ vv_g, const float* __restrict__ ww_g,
    const float* __restrict__ bo_g, float* __restrict__ out)
{
    __shared__ __align__(16) float s_in[2][5][16][64];  // [buf][arr][step][j]
    __shared__ __align__(16) float s_sk[2][64];

    const int bh = blockIdx.x;
    const int b = bh >> 4, h = bh & 15;
    const int tid = threadIdx.x;
    const int i  = tid >> 2;
    const int jq = tid & 3;
    const int jb = jq * 16;
    const size_t base = (size_t)bh * 2048 * 64;
    const float* arrs[5] = { rr, kk_g, vv_g, ww_g, bo_g };

    float S[16];
#pragma unroll
    for (int u = 0; u < 16; ++u) S[u] = 0.f;

    const int st_ld  = tid >> 4;        // 0..15 (step within window)
    const int off_ld = (tid & 15) * 4;  // float offset within row

    // prefetch windows 0 and 1
#pragma unroll
    for (int wv = 0; wv < 2; ++wv) {
#pragma unroll
        for (int a = 0; a < 5; ++a)
            cp_async16(&s_in[wv][a][st_ld][off_ld],
                       arrs[a] + base + (size_t)(wv * 16 + st_ld) * 64 + off_ld);
        cp_commit();
    }

    for (int win = 0; win < 128; ++win) {
        const int buf = win & 1;
        if (win >= 126) cp_wait0(); else cp_wait1();
        __syncthreads();

#pragma unroll 1
        for (int st = 0; st < 16; ++st) {
            const int l = win * 16 + st;
            const float* bs = &s_in[buf][0][st][0];  // r
            const float* kk = bs + 1024;             // k
            const float* vv = bs + 2048;             // v
            // k values for my 16 columns
            float kr[16];
            *(float4*)&kr[0]  = *(const float4*)(kk + jb + 0);
            *(float4*)&kr[4]  = *(const float4*)(kk + jb + 4);
            *(float4*)&kr[8]  = *(const float4*)(kk + jb + 8);
            *(float4*)&kr[12] = *(const float4*)(kk + jb + 12);

            // partial Sk_i over my column chunk
            float acc = 0.f;
#pragma unroll
            for (int u = 0; u < 16; ++u) acc = fmaf(S[u], kr[u], acc);
            acc += __shfl_xor_sync(0xffffffffu, acc, 1);
            acc += __shfl_xor_sync(0xffffffffu, acc, 2);   // full Sk_i in all 4 lanes

            const int par = l & 1;
            if (jq == 0) s_sk[par][i] = acc;
            __syncthreads();

            const float wi = bs[3 * 1024 + i];
            const float ki = kk[i];
            const float ci = bs[4 * 1024 + i] * ki;
            const float ri = bs[i];

            float d[16];
            float dk = 0.f;
#pragma unroll
            for (int u4 = 0; u4 < 16; u4 += 4) {
                float4 vv4 = *(const float4*)(vv + jb + u4);
                float4 sk4 = *(const float4*)(&s_sk[par][jb + u4]);
                d[u4 + 0] = vv4.x - sk4.x;
                d[u4 + 1] = vv4.y - sk4.y;
                d[u4 + 2] = vv4.z - sk4.z;
                d[u4 + 3] = vv4.w - sk4.w;
            }
#pragma unroll
            for (int u = 0; u < 16; ++u) dk = fmaf(d[u], kr[u], dk);
            dk += __shfl_xor_sync(0xffffffffu, dk, 1);
            dk += __shfl_xor_sync(0xffffffffu, dk, 2);

#pragma unroll
            for (int u = 0; u < 16; ++u) S[u] = fmaf(ci, d[u], S[u] * wi);

            if (jq == 0) {
                float y = ri * fmaf(ci, dk, wi * acc);
                out[(size_t)(b * 2048 + l) * 1024 + h * 64 + i] = y;  // pure write
            }
        }
        __syncthreads();
        if (win + 2 < 128) {
#pragma unroll
            for (int a = 0; a < 5; ++a)
                cp_async16(&s_in[buf][a][st_ld][off_ld],
                           arrs[a] + base + (size_t)((win + 2) * 16 + st_ld) * 64 + off_ld);
            cp_commit();
        }
    }
}

// ============================================================================
// K1: per-chunk SSD work. grid = 1024 (b,c,h), 256 threads, dynamic smem.
//   G[l,s] = (C_l . B_s) * eA[l]*ieA[s]  (s<=l else 0)
//   Y_diag[l,p] = sum_s G[l,s] X[s,p]        -> out += (RMW)
//   states[p,n] = sum_l B[l,n]*ds[l]*X[l,p]  -> g_states
//   ds[l] = eA[63]*ieA[l]
// ============================================================================
__global__ void __launch_bounds__(256) ssd_chunk_kernel(
    const float* __restrict__ X, const float* __restrict__ A,
    const float* __restrict__ Bm, const float* __restrict__ Cm,
    float* __restrict__ out)
{
    extern __shared__ float sm[];
    float* sB   = sm;                 // [64][65] (padded: strided lane reads)
    float* sG   = sm + 64 * 65;       // [64][65] C tile, later overwritten by G
    float* sX   = sm + 2 * 64 * 65;   // [64][64]
    float* s_cum = sX + 4096;         // [64]
    float* s_eA  = s_cum + 64;        // [64]
    float* s_ieA = s_eA + 64;         // [64]

    const int blk = blockIdx.x;               // b*512 + cc*16 + h
    const int h  = blk & 15;
    const int cc = (blk >> 4) & 31;
    const int b  = blk >> 9;
    const int tid = threadIdx.x;

    const size_t gbase = ((size_t)(b * 2048 + cc * 64) * 16 + h) * 64;
#pragma unroll
    for (int u = 0; u < 4; ++u) {
        int idx4 = u * 256 + tid;             // 0..1023
        int l = idx4 >> 4, n4 = (idx4 & 15) * 4;
        size_t go = gbase + (size_t)l * 1024 + n4;
        float4 bv = *(const float4*)(Bm + go);
        float4 cv = *(const float4*)(Cm + go);
        float4 xv = *(const float4*)(X + go);
        float* pb = sB + l * 65 + n4;
        pb[0] = bv.x; pb[1] = bv.y; pb[2] = bv.z; pb[3] = bv.w;
        float* pc = sG + l * 65 + n4;
        pc[0] = cv.x; pc[1] = cv.y; pc[2] = cv.z; pc[3] = cv.w;
        *(float4*)(sX + l * 64 + n4) = xv;
    }
    if (tid < 64) {
        float x = A[(size_t)(b * 2048 + cc * 64 + tid) * 16 + h];
#pragma unroll
        for (int o = 1; o < 32; o <<= 1) {
            float t = __shfl_up_sync(0xffffffffu, x, o);
            if ((tid & 31) >= o) x += t;
        }
        s_cum[tid] = x;
    }
    __syncthreads();
    if (tid < 64) {
        float x = s_cum[tid] + ((tid >= 32) ? s_cum[31] : 0.f);
        float e = expf(x);
        s_eA[tid]  = e;
        s_ieA[tid] = expf(-x);
        g_eA[(size_t)blk * 64 + tid] = e;
        if (tid == 63) g_expsA[(b * 16 + h) * 32 + cc] = e;
    }
    __syncthreads();

    const int tl = tid >> 4, ts = tid & 15;
    const int r0 = tl * 4, c0 = ts * 4;

    // ---- Phase G: dot(C_l, B_s) ----
    float g[4][4];
#pragma unroll
    for (int ii = 0; ii < 4; ++ii)
#pragma unroll
        for (int jj = 0; jj < 4; ++jj) g[ii][jj] = 0.f;

    for (int n = 0; n < 64; ++n) {
        float cl[4], bsv[4];
#pragma unroll
        for (int ii = 0; ii < 4; ++ii) cl[ii] = sG[(r0 + ii) * 65 + n];
#pragma unroll
        for (int jj = 0; jj < 4; ++jj) bsv[jj] = sB[(c0 + jj) * 65 + n];
#pragma unroll
        for (int ii = 0; ii < 4; ++ii)
#pragma unroll
            for (int jj = 0; jj < 4; ++jj) g[ii][jj] = fmaf(cl[ii], bsv[jj], g[ii][jj]);
    }
    __syncthreads();  // all C reads done; now overwrite sG with masked/scaled G
#pragma unroll
    for (int ii = 0; ii < 4; ++ii) {
        int l = r0 + ii;
        float el = s_eA[l];
#pragma unroll
        for (int jj = 0; jj < 4; ++jj) {
            int s = c0 + jj;
            sG[l * 65 + s] = (s <= l) ? g[ii][jj] * el * s_ieA[s] : 0.f;
        }
    }
    __syncthreads();

    // ---- Phase Y_diag: y[l,p] = sum_s G[l,s]*X[s,p] ----
    float y[4][4];
#pragma unroll
    for (int ii = 0; ii < 4; ++ii)
#pragma unroll
        for (int jj = 0; jj < 4; ++jj) y[ii][jj] = 0.f;

    for (int s = 0; s < 64; ++s) {
        float4 xv = *(const float4*)(sX + s * 64 + c0);
        float gl[4];
#pragma unroll
        for (int ii = 0; ii < 4; ++ii) gl[ii] = sG[(r0 + ii) * 65 + s];
#pragma unroll
        for (int ii = 0; ii < 4; ++ii) {
            y[ii][0] = fmaf(gl[ii], xv.x, y[ii][0]);
            y[ii][1] = fmaf(gl[ii], xv.y, y[ii][1]);
            y[ii][2] = fmaf(gl[ii], xv.z, y[ii][2]);
            y[ii][3] = fmaf(gl[ii], xv.w, y[ii][3]);
        }
    }
#pragma unroll
    for (int ii = 0; ii < 4; ++ii) {
        int l = r0 + ii;
        float4* po = (float4*)(out + (size_t)(b * 2048 + cc * 64 + l) * 1024 + h * 64 + c0);
        float4 o = *po;
        o.x += y[ii][0]; o.y += y[ii][1]; o.z += y[ii][2]; o.w += y[ii][3];
        *po = o;
    }

    // ---- Phase states: st[p,n] = sum_l ds[l]*X[l,p]*B[l,n] ----
    float stt[4][4];
#pragma unroll
    for (int ii = 0; ii < 4; ++ii)
#pragma unroll
        for (int jj = 0; jj < 4; ++jj) stt[ii][jj] = 0.f;

    const float eA63 = s_eA[63];
    for (int l = 0; l < 64; ++l) {
        float ds = eA63 * s_ieA[l];
        float4 xv = *(const float4*)(sX + l * 64 + r0);
        float xw[4] = { xv.x * ds, xv.y * ds, xv.z * ds, xv.w * ds };
        float bv[4];
#pragma unroll
        for (int jj = 0; jj < 4; ++jj) bv[jj] = sB[l * 65 + c0 + jj];
#pragma unroll
        for (int ii = 0; ii < 4; ++ii)
#pragma unroll
            for (int jj = 0; jj < 4; ++jj) stt[ii][jj] = fmaf(xw[ii], bv[jj], stt[ii][jj]);
    }
#pragma unroll
    for (int ii = 0; ii < 4; ++ii) {
        float4 o = make_float4(stt[ii][0], stt[ii][1], stt[ii][2], stt[ii][3]);
        *(float4*)(g_states + (size_t)blk * 4096 + (size_t)(r0 + ii) * 64 + c0) = o;
    }
}

// ============================================================================
// K2: inter-chunk decay scan. R[0]=0; R[c+1] = R[c]*exp(chunk_sum[c]) + states[c].
// g_R[c] = state entering chunk c. 128 blocks x 1024 threads.
// ============================================================================
__global__ void __launch_bounds__(1024) scan_kernel()
{
    const int bid = blockIdx.x;
    const int bh = bid >> 2, q = bid & 3;
    const int b = bh >> 4, h = bh & 15;
    const int e = q * 1024 + threadIdx.x;   // p*64+n
    float R = 0.f;
    const float* es = g_expsA + bh * 32;
#pragma unroll 1
    for (int c = 0; c < 32; ++c) {
        size_t idx = (size_t)(b * 512 + c * 16 + h) * 4096 + e;
        g_R[idx] = R;
        R = fmaf(R, es[c], g_states[idx]);
    }
}

// ============================================================================
// K3: Y_off[l,p] = eA[l] * sum_n C[l,n]*R[p,n]  -> out += (RMW)
// ============================================================================
__global__ void __launch_bounds__(256) ssd_off_kernel(
    const float* __restrict__ Cm, float* __restrict__ out)
{
    __shared__ float sC[64 * 65];
    __shared__ float sR[64 * 65];
    __shared__ float s_e[64];
    const int blk = blockIdx.x;
    const int h  = blk & 15;
    const int cc = (blk >> 4) & 31;
    const int b  = blk >> 9;
    const int tid = threadIdx.x;

    const size_t gbase = ((size_t)(b * 2048 + cc * 64) * 16 + h) * 64;
#pragma unroll
    for (int u = 0; u < 4; ++u) {
        int idx4 = u * 256 + tid;
        int l = idx4 >> 4, n4 = (idx4 & 15) * 4;
        float4 cv = *(const float4*)(Cm + gbase + (size_t)l * 1024 + n4);
        float4 rv = *(const float4*)(g_R + (size_t)blk * 4096 + (size_t)idx4 * 4);
        float* pc = sC + l * 65 + n4;
        pc[0] = cv.x; pc[1] = cv.y; pc[2] = cv.z; pc[3] = cv.w;
        float* pr = sR + l * 65 + n4;  // here "l" row index == p for R
        pr[0] = rv.x; pr[1] = rv.y; pr[2] = rv.z; pr[3] = rv.w;
    }
    if (tid < 64) s_e[tid] = g_eA[(size_t)blk * 64 + tid];
    __syncthreads();

    const int tl = tid >> 4, ts = tid & 15;
    const int l0 = tl * 4, p0 = ts * 4;

    float acc[4][4];
#pragma unroll
    for (int ii = 0; ii < 4; ++ii)
#pragma unroll
        for (int jj = 0; jj < 4; ++jj) acc[ii][jj] = 0.f;

    for (int n = 0; n < 64; ++n) {
        float cl[4], rv[4];
#pragma unroll
        for (int ii = 0; ii < 4; ++ii) cl[ii] = sC[(l0 + ii) * 65 + n];
#pragma unroll
        for (int jj = 0; jj < 4; ++jj) rv[jj] = sR[(p0 + jj) * 65 + n];
#pragma unroll
        for (int ii = 0; ii < 4; ++ii)
#pragma unroll
            for (int jj = 0; jj < 4; ++jj) acc[ii][jj] = fmaf(cl[ii], rv[jj], acc[ii][jj]);
    }
#pragma unroll
    for (int ii = 0; ii < 4; ++ii) {
        int l = l0 + ii;
        float e = s_e[l];
        float4* po = (float4*)(out + (size_t)(b * 2048 + cc * 64 + l) * 1024 + h * 64 + p0);
        float4 o = *po;
        o.x += e * acc[ii][0];
        o.y += e * acc[ii][1];
        o.z += e * acc[ii][2];
        o.w += e * acc[ii][3];
        *po = o;
    }
}

// ============================================================================
extern "C" void kernel_launch(void* const* d_in, const int* in_sizes, int n_in,
                              void* d_out, int out_size)
{
    (void)in_sizes; (void)n_in; (void)out_size;
    const float* X  = (const float*)d_in[0];
    const float* A  = (const float*)d_in[1];
    const float* B  = (const float*)d_in[2];
    const float* C  = (const float*)d_in[3];
    const float* r  = (const float*)d_in[4];
    const float* k  = (const float*)d_in[5];
    const float* v  = (const float*)d_in[6];
    const float* w  = (const float*)d_in[7];
    const float* bo = (const float*)d_in[8];
    float* out = (float*)d_out;

    const int K1_SMEM = (2 * 64 * 65 + 64 * 64 + 3 * 64) * 4;  // 50432 bytes
    cudaFuncSetAttribute(ssd_chunk_kernel,
                         cudaFuncAttributeMaxDynamicSharedMemorySize, K1_SMEM);

    // WKV first: it WRITES out (full coverage). SSD kernels then RMW-add.
    wkv_kernel<<<32, 256>>>(r, k, v, w, bo, out);
    ssd_chunk_kernel<<<1024, 256, K1_SMEM>>>(X, A, B, C, out);
    scan_kernel<<<128, 1024>>>();
    ssd_off_kernel<<<1024, 256>>>(C, out);
}